// round 11
// baseline (speedup 1.0000x reference)
#include <cuda_runtime.h>
#include <cuda_fp16.h>
#include <math.h>

#define NB   4
#define NS   160
#define NSS  (160*160)
#define NVOX (160*160*160)
#define ZCH  20
#define P1SLOTS 320        // pass-1 blocks per batch: 40*8
#define NBLK2  640         // pass-2 total blocks: 20*8*NB

// 1D gaussian taps, sigma=5, radius=4: exp(-i^2/50)
#define G_TAPS {0.72614904f,0.83527021f,0.92311635f,0.98019867f,1.0f,\
                0.98019867f,0.92311635f,0.83527021f,0.72614904f}

__device__ __forceinline__ __half2 u32_as_h2(unsigned u) {
    return *reinterpret_cast<__half2*>(&u);
}

__device__ __half2 g_q[(size_t)NB * NVOX / 2];   // (K_x * K_z * p), half2 per x-pair
__device__ unsigned g_pv[(size_t)NB * NVOX];     // per voxel: p(u16 lo) | v(u16 hi), fixed-point
__device__ double g_p1[NB * P1SLOTS * 3];        // pass-1 per-block (sp, sip, si)
__device__ double g_p2[NBLK2 * 4];               // pass-2 per-block (N0,D0,N1,D1)
__device__ unsigned g_cnt = 0;                   // self-resetting finalize counter

// conv-of-ones along one axis (zero padding): closed form
__device__ __forceinline__ float cfun(int i) {
    const float H[5] = {1.0f, 1.98019867f, 2.90331502f, 3.73858523f, 4.46473427f};
    int a = i < 4 ? i : 4;
    int c = (159 - i) < 4 ? (159 - i) : 4;
    return H[a] + H[c] - 1.0f;
}

// Pass 1: stream lab/inp along z. Per z-step: fused fp32 mean sums, u16 (p,v)
// pack, z-conv (fp16 ring), smem row, x-conv (paired taps) -> zx-convolved q.
__global__ void __launch_bounds__(320) k_A(const float* __restrict__ lab,
                                           const float* __restrict__ inp) {
    const float G[9] = G_TAPS;
    __half2 G2[9];
    #pragma unroll
    for (int i = 0; i < 9; i++) G2[i] = __float2half2_rn(G[i]);
    __half2 TE[5], TO[5];
    TE[0] = __floats2half2_rn(G[0], G[1]); TE[1] = __floats2half2_rn(G[2], G[3]);
    TE[2] = __floats2half2_rn(G[4], G[5]); TE[3] = __floats2half2_rn(G[6], G[7]);
    TE[4] = __floats2half2_rn(G[8], 0.f);
    TO[0] = __floats2half2_rn(0.f, G[0]);  TO[1] = __floats2half2_rn(G[1], G[2]);
    TO[2] = __floats2half2_rn(G[3], G[4]); TO[3] = __floats2half2_rn(G[5], G[6]);
    TO[4] = __floats2half2_rn(G[7], G[8]);

    int hx = threadIdx.x;                 // 0..79 (x pair)
    int ty = threadIdx.y;                 // 0..3
    int y  = blockIdx.x * 4 + ty;
    int z0 = blockIdx.y * ZCH;
    int b  = blockIdx.z;

    size_t rowbase = (size_t)b * NVOX + (size_t)y * NS;   // voxel index of (b,z=0,y,x=0)
    const float2* Lp = (const float2*)(lab + rowbase) + hx;
    const float2* Vp = (const float2*)(inp + rowbase) + hx;
    uint2*  PV = (uint2*)g_pv + rowbase / 2 + hx;         // + z*NSS/2 per step (u32/voxel)
    __half2* Q = g_q + rowbase / 2 + hx;                  // + z*NSS/2 per step

    __shared__ __half2 srow[4][2][84];    // [ty][buf][hx+2], pads at 0,1,82,83
    const __half2 h2z = __float2half2_rn(0.f);
    if (hx < 2) {
        srow[ty][0][hx] = h2z;       srow[ty][1][hx] = h2z;
        srow[ty][0][82 + hx] = h2z;  srow[ty][1][82 + hx] = h2z;
    }

    __half2 ring[9];
    float2 fring[5];                      // fp32 p delay line (center at fring[0])
    #pragma unroll
    for (int i = 0; i < 8; i++) {
        int z = z0 - 4 + i;
        float2 f = make_float2(0.f, 0.f);
        if (z >= 0) f = Lp[(size_t)z * (NSS / 2)];
        ring[i] = __floats2half2_rn(f.x, f.y);
        if (i >= 4) fring[i - 4] = f;     // rows z0..z0+3
    }

    float sp = 0.f, sip = 0.f, si = 0.f;

    #pragma unroll 4
    for (int j = 0; j < ZCH; ++j) {
        int z  = z0 + j;
        int zl = z + 4;
        float2 f = make_float2(0.f, 0.f);
        if (zl < NS) f = Lp[(size_t)zl * (NSS / 2)];
        ring[8]  = __floats2half2_rn(f.x, f.y);
        fring[4] = f;

        // exact fp32 sums + u16 fixed-point (p,v) pack at current z
        float2 vc = Vp[(size_t)z * (NSS / 2)];
        float2 pc = fring[0];
        sp  += pc.x + pc.y;
        sip += vc.x * pc.x + vc.y * pc.y;
        si  += vc.x + vc.y;
        unsigned pu0 = __float2uint_rn(pc.x * 65535.f);
        unsigned vu0 = __float2uint_rn(vc.x * 65535.f);
        unsigned pu1 = __float2uint_rn(pc.y * 65535.f);
        unsigned vu1 = __float2uint_rn(vc.y * 65535.f);
        uint2 pvw;
        pvw.x = pu0 | (vu0 << 16);
        pvw.y = pu1 | (vu1 << 16);
        PV[(size_t)z * (NSS / 2)] = pvw;

        // z-conv (fp16)
        __half2 s = __hmul2(G2[0], ring[0]);
        #pragma unroll
        for (int i = 1; i < 9; i++) s = __hfma2(G2[i], ring[i], s);

        int bf = j & 1;
        srow[ty][bf][hx + 2] = s;
        __syncthreads();

        // x-conv (even/odd paired taps on half2 row)
        __half2 h0 = srow[ty][bf][hx + 0];
        __half2 h1 = srow[ty][bf][hx + 1];
        __half2 h2 = srow[ty][bf][hx + 2];
        __half2 h3 = srow[ty][bf][hx + 3];
        __half2 h4 = srow[ty][bf][hx + 4];
        __half2 se = __hmul2(TE[0], h0);
        se = __hfma2(TE[1], h1, se); se = __hfma2(TE[2], h2, se);
        se = __hfma2(TE[3], h3, se); se = __hfma2(TE[4], h4, se);
        __half2 so = __hmul2(TO[0], h0);
        so = __hfma2(TO[1], h1, so); so = __hfma2(TO[2], h2, so);
        so = __hfma2(TO[3], h3, so); so = __hfma2(TO[4], h4, so);
        float2 fe = __half22float2(se);
        float2 fo = __half22float2(so);
        Q[(size_t)z * (NSS / 2)] = __floats2half2_rn(fe.x + fe.y, fo.x + fo.y);

        #pragma unroll
        for (int i = 0; i < 8; i++) ring[i] = ring[i + 1];
        #pragma unroll
        for (int i = 0; i < 4; i++) fring[i] = fring[i + 1];
    }

    // block-reduce the three sums, write partial slot (no atomics)
    double a = sp, c = sip, d = si;
    #pragma unroll
    for (int o = 16; o > 0; o >>= 1) {
        a += __shfl_down_sync(0xffffffffu, a, o);
        c += __shfl_down_sync(0xffffffffu, c, o);
        d += __shfl_down_sync(0xffffffffu, d, o);
    }
    __shared__ double sm[3][10];
    int tid = ty * 80 + hx;
    int w = tid >> 5, l = tid & 31;
    if (l == 0) { sm[0][w] = a; sm[1][w] = c; sm[2][w] = d; }
    __syncthreads();
    if (tid == 0) {
        double aa = 0, cc = 0, dd = 0;
        for (int i = 0; i < 10; i++) { aa += sm[0][i]; cc += sm[1][i]; dd += sm[2][i]; }
        int pb = ((b * 8 + blockIdx.y) * 40 + blockIdx.x) * 3;
        g_p1[pb + 0] = aa;
        g_p1[pb + 1] = cc;
        g_p1[pb + 2] = dd;
    }
}

// Pass 2: barrier-free streaming. Each thread owns 4 x (2 half2 ring chains),
// rings over y on q, decodes u16 (p,v), computes weights + all four dots.
__global__ void __launch_bounds__(320) k_C(float* __restrict__ out) {
    const float G[9] = G_TAPS;
    __half2 G2[9];
    #pragma unroll
    for (int i = 0; i < 9; i++) G2[i] = __float2half2_rn(G[i]);

    int tx = threadIdx.x;          // 0..39 (4 x each)
    int tz = threadIdx.y;          // 0..7
    int z  = blockIdx.x * 8 + tz;
    int y0 = blockIdx.y * ZCH;
    int b  = blockIdx.z;
    int tid = tz * 40 + tx;

    // means from pass-1 partials (warp 0 sums 320 slots)
    __shared__ float s_m[2];
    if (tid < 32) {
        double a = 0, c = 0, d = 0;
        for (int i = tid; i < P1SLOTS; i += 32) {
            int base = (b * P1SLOTS + i) * 3;
            a += g_p1[base + 0]; c += g_p1[base + 1]; d += g_p1[base + 2];
        }
        #pragma unroll
        for (int o = 16; o > 0; o >>= 1) {
            a += __shfl_down_sync(0xffffffffu, a, o);
            c += __shfl_down_sync(0xffffffffu, c, o);
            d += __shfl_down_sync(0xffffffffu, d, o);
        }
        if (tid == 0) {
            const double Nv = (double)NVOX;
            s_m[0] = (float)((c / Nv) / (a / Nv + 1e-5));
            s_m[1] = (float)(((d - c) / Nv) / ((Nv - a) / Nv + 1e-5));
        }
    }
    __syncthreads();
    float m0 = s_m[0], m1 = s_m[1];

    float cz = cfun(z);
    float cc0 = cfun(4 * tx + 0) * cz;
    float cc1 = cfun(4 * tx + 1) * cz;
    float cc2 = cfun(4 * tx + 2) * cz;
    float cc3 = cfun(4 * tx + 3) * cz;

    size_t plane = (size_t)b * NVOX + (size_t)z * NSS;
    const uint2* Qr  = (const uint2*)g_q + plane / 4 + tx;   // uint2 = 2 half2 = 4 x; 40/row
    const uint4* PVr = (const uint4*)g_pv + plane / 4 + tx;  // uint4 = 4 u32 = 4 voxels; 40/row

    __half2 r0[9], r1[9];
    const __half2 h2z = __float2half2_rn(0.f);
    #pragma unroll
    for (int i = 0; i < 8; i++) {
        int y = y0 - 4 + i;
        __half2 a = h2z, c = h2z;
        if (y >= 0) {
            uint2 qw = Qr[(size_t)y * (NS / 4)];
            a = u32_as_h2(qw.x);
            c = u32_as_h2(qw.y);
        }
        r0[i] = a; r1[i] = c;
    }

    float aD0 = 0.f, aN0 = 0.f, aD1 = 0.f, aN1 = 0.f;
    const float S = 1.f / 65535.f;

    #pragma unroll 4
    for (int j = 0; j < ZCH; ++j) {
        int y  = y0 + j;
        int yl = y + 4;
        __half2 a = h2z, c = h2z;
        if (yl < NS) {
            uint2 qw = Qr[(size_t)yl * (NS / 4)];
            a = u32_as_h2(qw.x);
            c = u32_as_h2(qw.y);
        }
        r0[8] = a; r1[8] = c;

        __half2 s0 = __hmul2(G2[0], r0[0]);
        __half2 s1 = __hmul2(G2[0], r1[0]);
        #pragma unroll
        for (int i = 1; i < 9; i++) {
            s0 = __hfma2(G2[i], r0[i], s0);
            s1 = __hfma2(G2[i], r1[i], s1);
        }
        float2 qa = __half22float2(s0);    // q at x=4tx, 4tx+1
        float2 qb = __half22float2(s1);    // q at x=4tx+2, 4tx+3

        float cy = cfun(y);
        float qc0 = cc0 * cy - qa.x;
        float qc1 = cc1 * cy - qa.y;
        float qc2 = cc2 * cy - qb.x;
        float qc3 = cc3 * cy - qb.y;

        uint4 pvw = PVr[(size_t)y * (NS / 4)];

        #define LANE(wrd, qv, qcv) { \
            float p = (float)((wrd) & 0xFFFFu) * S; \
            float v = (float)((wrd) >> 16) * S; \
            float d0 = v - m0; float u0 = d0 * d0; float w0 = __expf(-u0 * u0); \
            float d1 = v - m1; float u1 = d1 * d1; float w1 = __expf(-u1 * u1); \
            aD0 += w0 * qv;  aN0 += (p * w0) * qv; \
            aD1 += w1 * qcv; aN1 += ((1.f - p) * w1) * qcv; }
        LANE(pvw.x, qa.x, qc0)
        LANE(pvw.y, qa.y, qc1)
        LANE(pvw.z, qb.x, qc2)
        LANE(pvw.w, qb.y, qc3)
        #undef LANE

        #pragma unroll
        for (int i = 0; i < 8; i++) { r0[i] = r0[i + 1]; r1[i] = r1[i + 1]; }
    }

    // block-reduce four accumulators, write partial, last block finalizes
    double vn0 = aN0, vd0 = aD0, vn1 = aN1, vd1 = aD1;
    #pragma unroll
    for (int o = 16; o > 0; o >>= 1) {
        vn0 += __shfl_down_sync(0xffffffffu, vn0, o);
        vd0 += __shfl_down_sync(0xffffffffu, vd0, o);
        vn1 += __shfl_down_sync(0xffffffffu, vn1, o);
        vd1 += __shfl_down_sync(0xffffffffu, vd1, o);
    }
    __shared__ double sm[4][10];
    int w = tid >> 5, l = tid & 31;
    if (l == 0) { sm[0][w] = vn0; sm[1][w] = vd0; sm[2][w] = vn1; sm[3][w] = vd1; }
    __syncthreads();

    __shared__ int s_last;
    int bid = (b * 8 + blockIdx.y) * 20 + blockIdx.x;
    if (tid == 0) {
        double aa = 0, bb = 0, cc = 0, dd = 0;
        for (int i = 0; i < 10; i++) { aa += sm[0][i]; bb += sm[1][i]; cc += sm[2][i]; dd += sm[3][i]; }
        g_p2[bid * 4 + 0] = aa;
        g_p2[bid * 4 + 1] = bb;
        g_p2[bid * 4 + 2] = cc;
        g_p2[bid * 4 + 3] = dd;
        __threadfence();
        unsigned t = atomicAdd(&g_cnt, 1);
        s_last = (t == NBLK2 - 1);
    }
    __syncthreads();
    if (s_last) {
        double s0 = 0, s1 = 0, s2 = 0, s3 = 0;
        for (int i = tid; i < NBLK2; i += 320) {
            s0 += g_p2[i * 4 + 0];
            s1 += g_p2[i * 4 + 1];
            s2 += g_p2[i * 4 + 2];
            s3 += g_p2[i * 4 + 3];
        }
        #pragma unroll
        for (int o = 16; o > 0; o >>= 1) {
            s0 += __shfl_down_sync(0xffffffffu, s0, o);
            s1 += __shfl_down_sync(0xffffffffu, s1, o);
            s2 += __shfl_down_sync(0xffffffffu, s2, o);
            s3 += __shfl_down_sync(0xffffffffu, s3, o);
        }
        if (l == 0) { sm[0][w] = s0; sm[1][w] = s1; sm[2][w] = s2; sm[3][w] = s3; }
        __syncthreads();
        if (tid == 0) {
            double aa = 0, bb = 0, cc = 0, dd = 0;
            for (int i = 0; i < 10; i++) { aa += sm[0][i]; bb += sm[1][i]; cc += sm[2][i]; dd += sm[3][i]; }
            double loss = fabs(aa / (bb + 1e-6)) + fabs(cc / (dd + 1e-6));
            out[0] = (float)(2.0 - loss);
            g_cnt = 0;   // reset for next graph replay
        }
    }
}

extern "C" void kernel_launch(void* const* d_in, const int* in_sizes, int n_in,
                              void* d_out, int out_size) {
    const float* lab = (const float*)d_in[0];
    const float* inp = (const float*)d_in[1];
    float* out = (float*)d_out;

    k_A<<<dim3(40, 8, NB), dim3(80, 4)>>>(lab, inp);   // sums + zx-conv(p) + pv pack
    k_C<<<dim3(20, 8, NB), dim3(40, 8)>>>(out);        // y-conv + weights + dots + finalize
}

// round 12
// speedup vs baseline: 1.1604x; 1.1604x over previous
#include <cuda_runtime.h>
#include <cuda_fp16.h>
#include <math.h>

#define NB    4
#define NS    160
#define NSS   (160*160)
#define NVOX  (160*160*160)
#define ZCH   40
#define NBLK1 640          // pass-1 blocks: 40*4*NB
#define NBLK2 320          // pass-2 blocks: 20*4*NB

// 1D gaussian taps, sigma=5, radius=4: exp(-i^2/50)
#define G_TAPS {0.72614904f,0.83527021f,0.92311635f,0.98019867f,1.0f,\
                0.98019867f,0.92311635f,0.83527021f,0.72614904f}

__device__ __forceinline__ __half2 u32_as_h2(unsigned u) {
    return *reinterpret_cast<__half2*>(&u);
}
__device__ __forceinline__ unsigned h2_as_u32(__half2 h) {
    return *reinterpret_cast<unsigned*>(&h);
}

__device__ __half2  g_q[(size_t)NB * NVOX / 2];  // (K_x*K_z*p), half2 per x-pair
__device__ unsigned g_pv[(size_t)NB * NVOX];     // per voxel half2 (p,v) as u32
__device__ double   g_p1[NB * 160 * 3];          // pass-1 per-block (sp, sip, si)
__device__ float2   g_means[NB];                 // (m0, m1) per batch
__device__ double   g_p2[NBLK2 * 4];             // pass-2 per-block (N0,D0,N1,D1)
__device__ unsigned g_cntA = 0;                  // pass-1 finalize counter
__device__ unsigned g_cnt  = 0;                  // pass-2 finalize counter

// conv-of-ones along one axis (zero padding): closed form
__device__ __forceinline__ float cfun(int i) {
    const float H[5] = {1.0f, 1.98019867f, 2.90331502f, 3.73858523f, 4.46473427f};
    int a = i < 4 ? i : 4;
    int c = (159 - i) < 4 ? (159 - i) : 4;
    return H[a] + H[c] - 1.0f;
}

// Pass 1: stream lab/inp along z. Per z: exact fp32 mean sums, half2 (p,v) pack,
// z-conv (fp16 ring), smem row (2 z per barrier), x-conv -> zx-convolved q.
// Last block computes per-batch means.
__global__ void __launch_bounds__(320) k_A(const float* __restrict__ lab,
                                           const float* __restrict__ inp) {
    const float G[9] = G_TAPS;
    __half2 G2[9];
    #pragma unroll
    for (int i = 0; i < 9; i++) G2[i] = __float2half2_rn(G[i]);
    __half2 TE[5], TO[5];
    TE[0] = __floats2half2_rn(G[0], G[1]); TE[1] = __floats2half2_rn(G[2], G[3]);
    TE[2] = __floats2half2_rn(G[4], G[5]); TE[3] = __floats2half2_rn(G[6], G[7]);
    TE[4] = __floats2half2_rn(G[8], 0.f);
    TO[0] = __floats2half2_rn(0.f, G[0]);  TO[1] = __floats2half2_rn(G[1], G[2]);
    TO[2] = __floats2half2_rn(G[3], G[4]); TO[3] = __floats2half2_rn(G[5], G[6]);
    TO[4] = __floats2half2_rn(G[7], G[8]);

    int hx = threadIdx.x;                 // 0..79 (x pair)
    int ty = threadIdx.y;                 // 0..3
    int y  = blockIdx.x * 4 + ty;
    int z0 = blockIdx.y * ZCH;
    int b  = blockIdx.z;
    int tid = ty * 80 + hx;

    size_t rowbase = (size_t)b * NVOX + (size_t)y * NS;
    const float2* Lp = (const float2*)(lab + rowbase) + hx;
    const float2* Vp = (const float2*)(inp + rowbase) + hx;
    uint2*   PV = (uint2*)g_pv + rowbase / 2 + hx;     // uint2 = 2 voxels; 80/row
    __half2* Q  = g_q + rowbase / 2 + hx;              // half2 = 2 x; 80/row

    __shared__ __half2 srow[4][2][2][84];  // [ty][pair parity][sub][hx+2]
    const __half2 h2z = __float2half2_rn(0.f);
    if (hx < 2) {
        #pragma unroll
        for (int pp = 0; pp < 2; pp++)
            #pragma unroll
            for (int s = 0; s < 2; s++) {
                srow[ty][pp][s][hx] = h2z;
                srow[ty][pp][s][82 + hx] = h2z;
            }
    }

    __half2 ring[9];
    float2 fring[5];                      // fp32 p delay line, fring[0] = p(z)
    #pragma unroll
    for (int i = 0; i < 8; i++) {
        int z = z0 - 4 + i;
        float2 f = make_float2(0.f, 0.f);
        if (z >= 0) f = Lp[(size_t)z * (NSS / 2)];
        ring[i] = __floats2half2_rn(f.x, f.y);
        if (i >= 4) fring[i - 4] = f;
    }

    float sp = 0.f, sip = 0.f, si = 0.f;

    #pragma unroll 2
    for (int jp = 0; jp < ZCH / 2; ++jp) {
        int pp = jp & 1;
        #pragma unroll
        for (int s = 0; s < 2; ++s) {
            int z  = z0 + jp * 2 + s;
            int zl = z + 4;
            float2 f = make_float2(0.f, 0.f);
            if (zl < NS) f = Lp[(size_t)zl * (NSS / 2)];
            ring[8]  = __floats2half2_rn(f.x, f.y);
            fring[4] = f;

            float2 vc = Vp[(size_t)z * (NSS / 2)];
            float2 pc = fring[0];
            sp  += pc.x + pc.y;
            sip += vc.x * pc.x + vc.y * pc.y;
            si  += vc.x + vc.y;
            uint2 pvw;
            pvw.x = h2_as_u32(__halves2half2(__low2half(ring[4]),  __float2half_rn(vc.x)));
            pvw.y = h2_as_u32(__halves2half2(__high2half(ring[4]), __float2half_rn(vc.y)));
            PV[(size_t)z * (NSS / 2)] = pvw;

            __half2 sz = __hmul2(G2[0], ring[0]);
            #pragma unroll
            for (int i = 1; i < 9; i++) sz = __hfma2(G2[i], ring[i], sz);
            srow[ty][pp][s][hx + 2] = sz;

            #pragma unroll
            for (int i = 0; i < 8; i++) ring[i] = ring[i + 1];
            #pragma unroll
            for (int i = 0; i < 4; i++) fring[i] = fring[i + 1];
        }
        __syncthreads();
        #pragma unroll
        for (int s = 0; s < 2; ++s) {
            int z = z0 + jp * 2 + s;
            __half2 h0 = srow[ty][pp][s][hx + 0];
            __half2 h1 = srow[ty][pp][s][hx + 1];
            __half2 h2 = srow[ty][pp][s][hx + 2];
            __half2 h3 = srow[ty][pp][s][hx + 3];
            __half2 h4 = srow[ty][pp][s][hx + 4];
            __half2 se = __hmul2(TE[0], h0);
            se = __hfma2(TE[1], h1, se); se = __hfma2(TE[2], h2, se);
            se = __hfma2(TE[3], h3, se); se = __hfma2(TE[4], h4, se);
            __half2 so = __hmul2(TO[0], h0);
            so = __hfma2(TO[1], h1, so); so = __hfma2(TO[2], h2, so);
            so = __hfma2(TO[3], h3, so); so = __hfma2(TO[4], h4, so);
            float2 fe = __half22float2(se);
            float2 fo = __half22float2(so);
            Q[(size_t)z * (NSS / 2)] = __floats2half2_rn(fe.x + fe.y, fo.x + fo.y);
        }
    }

    // block-reduce sums -> slot; last block computes per-batch means
    double a = sp, c = sip, d = si;
    #pragma unroll
    for (int o = 16; o > 0; o >>= 1) {
        a += __shfl_down_sync(0xffffffffu, a, o);
        c += __shfl_down_sync(0xffffffffu, c, o);
        d += __shfl_down_sync(0xffffffffu, d, o);
    }
    __shared__ double sm[3][10];
    int w = tid >> 5, l = tid & 31;
    if (l == 0) { sm[0][w] = a; sm[1][w] = c; sm[2][w] = d; }
    __syncthreads();
    __shared__ int s_lastA;
    if (tid == 0) {
        double aa = 0, cc = 0, dd = 0;
        for (int i = 0; i < 10; i++) { aa += sm[0][i]; cc += sm[1][i]; dd += sm[2][i]; }
        int pb = ((b * 4 + blockIdx.y) * 40 + blockIdx.x) * 3;
        g_p1[pb + 0] = aa;
        g_p1[pb + 1] = cc;
        g_p1[pb + 2] = dd;
        __threadfence();
        unsigned t = atomicAdd(&g_cntA, 1);
        s_lastA = (t == NBLK1 - 1);
    }
    __syncthreads();
    if (s_lastA) {
        if (tid == 0) g_cntA = 0;
        if (w < 4) {                      // warp w handles batch w
            double aa = 0, cc = 0, dd = 0;
            for (int i = l; i < 160; i += 32) {
                int base = (w * 160 + i) * 3;
                aa += g_p1[base + 0]; cc += g_p1[base + 1]; dd += g_p1[base + 2];
            }
            #pragma unroll
            for (int o = 16; o > 0; o >>= 1) {
                aa += __shfl_down_sync(0xffffffffu, aa, o);
                cc += __shfl_down_sync(0xffffffffu, cc, o);
                dd += __shfl_down_sync(0xffffffffu, dd, o);
            }
            if (l == 0) {
                const double Nv = (double)NVOX;
                float m0 = (float)((cc / Nv) / (aa / Nv + 1e-5));
                float m1 = (float)(((dd - cc) / Nv) / ((Nv - aa) / Nv + 1e-5));
                g_means[w] = make_float2(m0, m1);
            }
        }
    }
}

// Pass 2: barrier-free streaming. Each thread owns 4 x, rings over y on q with
// explicit next-row prefetch, decodes half2 (p,v), computes weights + dots.
__global__ void __launch_bounds__(320) k_C(float* __restrict__ out) {
    const float G[9] = G_TAPS;
    __half2 G2[9];
    #pragma unroll
    for (int i = 0; i < 9; i++) G2[i] = __float2half2_rn(G[i]);

    int tx = threadIdx.x;          // 0..39 (4 x each)
    int tz = threadIdx.y;          // 0..7
    int z  = blockIdx.x * 8 + tz;
    int y0 = blockIdx.y * ZCH;
    int b  = blockIdx.z;
    int tid = tz * 40 + tx;

    float2 mm = g_means[b];
    float m0 = mm.x, m1 = mm.y;

    float cz = cfun(z);
    float cc0 = cfun(4 * tx + 0) * cz;
    float cc1 = cfun(4 * tx + 1) * cz;
    float cc2 = cfun(4 * tx + 2) * cz;
    float cc3 = cfun(4 * tx + 3) * cz;

    const int QS = NS / 4;   // 40 (uint2 per q row; uint4 per pv row)
    size_t plane = (size_t)b * NVOX + (size_t)z * NSS;
    const uint2* Qr  = (const uint2*)g_q + plane / 4 + tx;
    const uint4* PVr = (const uint4*)g_pv + plane / 4 + tx;

    __half2 r0[9], r1[9];
    const __half2 h2z = __float2half2_rn(0.f);
    #pragma unroll
    for (int i = 0; i < 8; i++) {
        int yy = y0 - 4 + i;
        __half2 a = h2z, c = h2z;
        if (yy >= 0) {
            uint2 qw0 = Qr[(size_t)yy * QS];
            a = u32_as_h2(qw0.x);
            c = u32_as_h2(qw0.y);
        }
        r0[i] = a; r1[i] = c;
    }

    // primed loads for j=0
    uint2 qw = make_uint2(0u, 0u);
    { int yl = y0 + 4; if (yl < NS) qw = Qr[(size_t)yl * QS]; }
    uint4 pvw = PVr[(size_t)y0 * QS];

    float aD0 = 0.f, aN0 = 0.f, aD1 = 0.f, aN1 = 0.f;

    #pragma unroll 8
    for (int j = 0; j < ZCH; ++j) {
        int y = y0 + j;

        // prefetch next row pair
        uint2 qw_n = make_uint2(0u, 0u);
        int yn = y + 5;
        if (yn < NS) qw_n = Qr[(size_t)yn * QS];
        int yp = y + 1; if (yp > NS - 1) yp = NS - 1;
        uint4 pvw_n = PVr[(size_t)yp * QS];

        r0[8] = u32_as_h2(qw.x);
        r1[8] = u32_as_h2(qw.y);

        __half2 s0 = __hmul2(G2[0], r0[0]);
        __half2 s1 = __hmul2(G2[0], r1[0]);
        #pragma unroll
        for (int i = 1; i < 9; i++) {
            s0 = __hfma2(G2[i], r0[i], s0);
            s1 = __hfma2(G2[i], r1[i], s1);
        }
        float2 qa = __half22float2(s0);
        float2 qb = __half22float2(s1);

        float cy = cfun(y);
        float qc0 = cc0 * cy - qa.x;
        float qc1 = cc1 * cy - qa.y;
        float qc2 = cc2 * cy - qb.x;
        float qc3 = cc3 * cy - qb.y;

        #define LANE(wrd, qv, qcv) { \
            float2 pv = __half22float2(u32_as_h2(wrd)); \
            float p = pv.x, v = pv.y; \
            float d0 = v - m0; float u0 = d0 * d0; float w0 = __expf(-u0 * u0); \
            float d1 = v - m1; float u1 = d1 * d1; float w1 = __expf(-u1 * u1); \
            aD0 += w0 * qv;  aN0 += (p * w0) * qv; \
            aD1 += w1 * qcv; aN1 += ((1.f - p) * w1) * qcv; }
        LANE(pvw.x, qa.x, qc0)
        LANE(pvw.y, qa.y, qc1)
        LANE(pvw.z, qb.x, qc2)
        LANE(pvw.w, qb.y, qc3)
        #undef LANE

        #pragma unroll
        for (int i = 0; i < 8; i++) { r0[i] = r0[i + 1]; r1[i] = r1[i + 1]; }
        qw = qw_n; pvw = pvw_n;
    }

    // block-reduce four accumulators, write partial, last block finalizes
    double vn0 = aN0, vd0 = aD0, vn1 = aN1, vd1 = aD1;
    #pragma unroll
    for (int o = 16; o > 0; o >>= 1) {
        vn0 += __shfl_down_sync(0xffffffffu, vn0, o);
        vd0 += __shfl_down_sync(0xffffffffu, vd0, o);
        vn1 += __shfl_down_sync(0xffffffffu, vn1, o);
        vd1 += __shfl_down_sync(0xffffffffu, vd1, o);
    }
    __shared__ double sm[4][10];
    int w = tid >> 5, l = tid & 31;
    if (l == 0) { sm[0][w] = vn0; sm[1][w] = vd0; sm[2][w] = vn1; sm[3][w] = vd1; }
    __syncthreads();

    __shared__ int s_last;
    int bid = (b * 4 + blockIdx.y) * 20 + blockIdx.x;
    if (tid == 0) {
        double aa = 0, bb = 0, cc = 0, dd = 0;
        for (int i = 0; i < 10; i++) { aa += sm[0][i]; bb += sm[1][i]; cc += sm[2][i]; dd += sm[3][i]; }
        g_p2[bid * 4 + 0] = aa;
        g_p2[bid * 4 + 1] = bb;
        g_p2[bid * 4 + 2] = cc;
        g_p2[bid * 4 + 3] = dd;
        __threadfence();
        unsigned t = atomicAdd(&g_cnt, 1);
        s_last = (t == NBLK2 - 1);
    }
    __syncthreads();
    if (s_last) {
        double s0 = 0, s1 = 0, s2 = 0, s3 = 0;
        for (int i = tid; i < NBLK2; i += 320) {
            s0 += g_p2[i * 4 + 0];
            s1 += g_p2[i * 4 + 1];
            s2 += g_p2[i * 4 + 2];
            s3 += g_p2[i * 4 + 3];
        }
        #pragma unroll
        for (int o = 16; o > 0; o >>= 1) {
            s0 += __shfl_down_sync(0xffffffffu, s0, o);
            s1 += __shfl_down_sync(0xffffffffu, s1, o);
            s2 += __shfl_down_sync(0xffffffffu, s2, o);
            s3 += __shfl_down_sync(0xffffffffu, s3, o);
        }
        if (l == 0) { sm[0][w] = s0; sm[1][w] = s1; sm[2][w] = s2; sm[3][w] = s3; }
        __syncthreads();
        if (tid == 0) {
            double aa = 0, bb = 0, cc = 0, dd = 0;
            for (int i = 0; i < 10; i++) { aa += sm[0][i]; bb += sm[1][i]; cc += sm[2][i]; dd += sm[3][i]; }
            double loss = fabs(aa / (bb + 1e-6)) + fabs(cc / (dd + 1e-6));
            out[0] = (float)(2.0 - loss);
            g_cnt = 0;   // reset for next graph replay
        }
    }
}

extern "C" void kernel_launch(void* const* d_in, const int* in_sizes, int n_in,
                              void* d_out, int out_size) {
    const float* lab = (const float*)d_in[0];
    const float* inp = (const float*)d_in[1];
    float* out = (float*)d_out;

    k_A<<<dim3(40, 4, NB), dim3(80, 4)>>>(lab, inp);   // sums + zx-conv(p) + pv pack + means
    k_C<<<dim3(20, 4, NB), dim3(40, 8)>>>(out);        // y-conv + weights + dots + finalize
}

// round 14
// speedup vs baseline: 1.1742x; 1.0119x over previous
#include <cuda_runtime.h>
#include <cuda_fp16.h>
#include <math.h>

#define NB    4
#define NS    160
#define NSS   (160*160)
#define NVOX  (160*160*160)
#define ZCH   40
#define NBLK1 640          // pass-1 blocks: 40*4*NB
#define NBLK2 640          // pass-2 blocks: 40*4*NB

// 1D gaussian taps, sigma=5, radius=4: exp(-i^2/50)
#define G_TAPS {0.72614904f,0.83527021f,0.92311635f,0.98019867f,1.0f,\
                0.98019867f,0.92311635f,0.83527021f,0.72614904f}

__device__ __forceinline__ __half2 u32_as_h2(unsigned u) {
    return *reinterpret_cast<__half2*>(&u);
}
__device__ __forceinline__ unsigned h2_as_u32(__half2 h) {
    return *reinterpret_cast<unsigned*>(&h);
}

__device__ __half2  g_q[(size_t)NB * NVOX / 2];  // (K_x*K_z*p), half2 per x-pair
__device__ unsigned g_pv[(size_t)NB * NVOX];     // per voxel half2 (p,v) as u32
__device__ double   g_p1[NB * 160 * 3];          // pass-1 per-block (sp, sip, si)
__device__ float2   g_means[NB];                 // (m0, m1) per batch
__device__ double   g_p2[NBLK2 * 4];             // pass-2 per-block (N0,D0,N1,D1)
__device__ unsigned g_cntA = 0;                  // pass-1 finalize counter
__device__ unsigned g_cnt  = 0;                  // pass-2 finalize counter

// conv-of-ones along one axis (zero padding): closed form
__device__ __forceinline__ float cfun(int i) {
    const float H[5] = {1.0f, 1.98019867f, 2.90331502f, 3.73858523f, 4.46473427f};
    int a = i < 4 ? i : 4;
    int c = (159 - i) < 4 ? (159 - i) : 4;
    return H[a] + H[c] - 1.0f;
}

// Pass 1 (R9 structure, fixed indexing): stream lab/inp along z. Per z: mean
// sums (fp16 p from ring center), half2 (p,v) pack, z-conv, smem row, x-conv
// -> zx-convolved q. Last block computes per-batch means.
__global__ void __launch_bounds__(320) k_A(const float* __restrict__ lab,
                                           const float* __restrict__ inp) {
    const float G[9] = G_TAPS;
    __half2 G2[9];
    #pragma unroll
    for (int i = 0; i < 9; i++) G2[i] = __float2half2_rn(G[i]);
    __half2 TE[5], TO[5];
    TE[0] = __floats2half2_rn(G[0], G[1]); TE[1] = __floats2half2_rn(G[2], G[3]);
    TE[2] = __floats2half2_rn(G[4], G[5]); TE[3] = __floats2half2_rn(G[6], G[7]);
    TE[4] = __floats2half2_rn(G[8], 0.f);
    TO[0] = __floats2half2_rn(0.f, G[0]);  TO[1] = __floats2half2_rn(G[1], G[2]);
    TO[2] = __floats2half2_rn(G[3], G[4]); TO[3] = __floats2half2_rn(G[5], G[6]);
    TO[4] = __floats2half2_rn(G[7], G[8]);

    int hx = threadIdx.x;                 // 0..79 (x pair)
    int ty = threadIdx.y;                 // 0..3
    int y  = blockIdx.x * 4 + ty;
    int z0 = blockIdx.y * ZCH;
    int b  = blockIdx.z;
    int tid = ty * 80 + hx;

    size_t rowbase = (size_t)b * NVOX + (size_t)y * NS;
    const float2* Lp = (const float2*)(lab + rowbase) + hx;
    const float2* Vp = (const float2*)(inp + rowbase) + hx;
    uint2*   PV = (uint2*)g_pv + rowbase / 2 + hx;     // uint2 = 2 voxels; 80/row
    __half2* Q  = g_q + rowbase / 2 + hx;              // half2 = 2 x; 80/row

    __shared__ __half2 srow[4][2][84];    // [ty][buf][hx+2], pads at 0,1,82,83
    const __half2 h2z = __float2half2_rn(0.f);
    if (hx < 2) {
        srow[ty][0][hx] = h2z;       srow[ty][1][hx] = h2z;
        srow[ty][0][82 + hx] = h2z;  srow[ty][1][82 + hx] = h2z;
    }

    __half2 ring[9];
    #pragma unroll
    for (int i = 0; i < 8; i++) {
        int z = z0 - 4 + i;
        float2 f = make_float2(0.f, 0.f);
        if (z >= 0) f = Lp[(size_t)z * (NSS / 2)];
        ring[i] = __floats2half2_rn(f.x, f.y);
    }

    float sp = 0.f, sip = 0.f, si = 0.f;

    #pragma unroll 8
    for (int j = 0; j < ZCH; ++j) {
        int z  = z0 + j;
        int zl = z + 4;
        float2 f = make_float2(0.f, 0.f);
        if (zl < NS) f = Lp[(size_t)zl * (NSS / 2)];
        ring[8] = __floats2half2_rn(f.x, f.y);

        // sums + (p,v) pack at current z (ring[4] holds p)
        float2 vc = Vp[(size_t)z * (NSS / 2)];
        float2 pc = __half22float2(ring[4]);
        sp  += pc.x + pc.y;
        sip += vc.x * pc.x + vc.y * pc.y;
        si  += vc.x + vc.y;
        uint2 pvw;
        pvw.x = h2_as_u32(__halves2half2(__low2half(ring[4]),  __float2half_rn(vc.x)));
        pvw.y = h2_as_u32(__halves2half2(__high2half(ring[4]), __float2half_rn(vc.y)));
        PV[(size_t)z * (NSS / 2)] = pvw;

        // z-conv
        __half2 s = __hmul2(G2[0], ring[0]);
        #pragma unroll
        for (int i = 1; i < 9; i++) s = __hfma2(G2[i], ring[i], s);

        int bf = j & 1;
        srow[ty][bf][hx + 2] = s;
        __syncthreads();

        // x-conv (even/odd paired taps on half2 row)
        __half2 h0 = srow[ty][bf][hx + 0];
        __half2 h1 = srow[ty][bf][hx + 1];
        __half2 h2 = srow[ty][bf][hx + 2];
        __half2 h3 = srow[ty][bf][hx + 3];
        __half2 h4 = srow[ty][bf][hx + 4];
        __half2 se = __hmul2(TE[0], h0);
        se = __hfma2(TE[1], h1, se); se = __hfma2(TE[2], h2, se);
        se = __hfma2(TE[3], h3, se); se = __hfma2(TE[4], h4, se);
        __half2 so = __hmul2(TO[0], h0);
        so = __hfma2(TO[1], h1, so); so = __hfma2(TO[2], h2, so);
        so = __hfma2(TO[3], h3, so); so = __hfma2(TO[4], h4, so);
        float2 fe = __half22float2(se);
        float2 fo = __half22float2(so);
        Q[(size_t)z * (NSS / 2)] = __floats2half2_rn(fe.x + fe.y, fo.x + fo.y);

        #pragma unroll
        for (int i = 0; i < 8; i++) ring[i] = ring[i + 1];
    }

    // block-reduce sums -> slot; last block computes per-batch means
    double a = sp, c = sip, d = si;
    #pragma unroll
    for (int o = 16; o > 0; o >>= 1) {
        a += __shfl_down_sync(0xffffffffu, a, o);
        c += __shfl_down_sync(0xffffffffu, c, o);
        d += __shfl_down_sync(0xffffffffu, d, o);
    }
    __shared__ double sm[3][10];
    int w = tid >> 5, l = tid & 31;
    if (l == 0) { sm[0][w] = a; sm[1][w] = c; sm[2][w] = d; }
    __syncthreads();
    __shared__ int s_lastA;
    if (tid == 0) {
        double aa = 0, cc = 0, dd = 0;
        for (int i = 0; i < 10; i++) { aa += sm[0][i]; cc += sm[1][i]; dd += sm[2][i]; }
        int pb = ((b * 4 + blockIdx.y) * 40 + blockIdx.x) * 3;
        g_p1[pb + 0] = aa;
        g_p1[pb + 1] = cc;
        g_p1[pb + 2] = dd;
        __threadfence();
        unsigned t = atomicAdd(&g_cntA, 1);
        s_lastA = (t == NBLK1 - 1);
    }
    __syncthreads();
    if (s_lastA) {
        if (tid == 0) g_cntA = 0;
        if (w < 4) {                      // warp w handles batch w
            double aa = 0, cc = 0, dd = 0;
            for (int i = l; i < 160; i += 32) {
                int base = (w * 160 + i) * 3;
                aa += g_p1[base + 0]; cc += g_p1[base + 1]; dd += g_p1[base + 2];
            }
            #pragma unroll
            for (int o = 16; o > 0; o >>= 1) {
                aa += __shfl_down_sync(0xffffffffu, aa, o);
                cc += __shfl_down_sync(0xffffffffu, cc, o);
                dd += __shfl_down_sync(0xffffffffu, dd, o);
            }
            if (l == 0) {
                const double Nv = (double)NVOX;
                float m0 = (float)((cc / Nv) / (aa / Nv + 1e-5));
                float m1 = (float)(((dd - cc) / Nv) / ((Nv - aa) / Nv + 1e-5));
                g_means[w] = make_float2(m0, m1);
            }
        }
    }
}

// Pass 2: barrier-free streaming, 2 x per thread (80 tx). Single half2 ring
// chain over y on q with next-row prefetch; decode half2 (p,v); 4 dots.
__global__ void __launch_bounds__(320) k_C(float* __restrict__ out) {
    const float G[9] = G_TAPS;
    __half2 G2[9];
    #pragma unroll
    for (int i = 0; i < 9; i++) G2[i] = __float2half2_rn(G[i]);

    int tx = threadIdx.x;          // 0..79 (x pair: 2tx, 2tx+1)
    int tz = threadIdx.y;          // 0..3
    int z  = blockIdx.x * 4 + tz;
    int y0 = blockIdx.y * ZCH;
    int b  = blockIdx.z;
    int tid = tz * 80 + tx;

    float2 mm = g_means[b];
    float m0 = mm.x, m1 = mm.y;

    float cz  = cfun(z);
    float cc0 = cfun(2 * tx + 0) * cz;
    float cc1 = cfun(2 * tx + 1) * cz;

    const int QS = NS / 2;   // 80: u32 per q row / uint2 per pv row
    size_t plane = (size_t)b * NVOX + (size_t)z * NSS;
    const unsigned* Qr = (const unsigned*)g_q + plane / 2 + tx;
    const uint2*   PVr = (const uint2*)g_pv + plane / 2 + tx;

    __half2 r[9];
    const __half2 h2z = __float2half2_rn(0.f);
    #pragma unroll
    for (int i = 0; i < 8; i++) {
        int yy = y0 - 4 + i;
        r[i] = (yy >= 0) ? u32_as_h2(Qr[(size_t)yy * QS]) : h2z;
    }

    // primed loads for j=0
    unsigned qw = 0u;
    { int yl = y0 + 4; if (yl < NS) qw = Qr[(size_t)yl * QS]; }
    uint2 pvw = PVr[(size_t)y0 * QS];

    float aD0 = 0.f, aN0 = 0.f, aD1 = 0.f, aN1 = 0.f;

    #pragma unroll 8
    for (int j = 0; j < ZCH; ++j) {
        int y = y0 + j;

        // prefetch next row
        unsigned qw_n = 0u;
        int yn = y + 5;
        if (yn < NS) qw_n = Qr[(size_t)yn * QS];
        int yp = y + 1; if (yp > NS - 1) yp = NS - 1;
        uint2 pvw_n = PVr[(size_t)yp * QS];

        r[8] = u32_as_h2(qw);

        __half2 s0 = __hmul2(G2[0], r[0]);
        #pragma unroll
        for (int i = 1; i < 9; i++) s0 = __hfma2(G2[i], r[i], s0);
        float2 qa = __half22float2(s0);

        float cy = cfun(y);
        float qc0 = cc0 * cy - qa.x;
        float qc1 = cc1 * cy - qa.y;

        #define LANE(wrd, qv, qcv) { \
            float2 pv = __half22float2(u32_as_h2(wrd)); \
            float p = pv.x, v = pv.y; \
            float d0 = v - m0; float u0 = d0 * d0; float w0 = __expf(-u0 * u0); \
            float d1 = v - m1; float u1 = d1 * d1; float w1 = __expf(-u1 * u1); \
            aD0 += w0 * qv;  aN0 += (p * w0) * qv; \
            aD1 += w1 * qcv; aN1 += ((1.f - p) * w1) * qcv; }
        LANE(pvw.x, qa.x, qc0)
        LANE(pvw.y, qa.y, qc1)
        #undef LANE

        #pragma unroll
        for (int i = 0; i < 8; i++) r[i] = r[i + 1];
        qw = qw_n; pvw = pvw_n;
    }

    // block-reduce four accumulators, write partial, last block finalizes
    double vn0 = aN0, vd0 = aD0, vn1 = aN1, vd1 = aD1;
    #pragma unroll
    for (int o = 16; o > 0; o >>= 1) {
        vn0 += __shfl_down_sync(0xffffffffu, vn0, o);
        vd0 += __shfl_down_sync(0xffffffffu, vd0, o);
        vn1 += __shfl_down_sync(0xffffffffu, vn1, o);
        vd1 += __shfl_down_sync(0xffffffffu, vd1, o);
    }
    __shared__ double sm[4][10];
    int w = tid >> 5, l = tid & 31;
    if (l == 0) { sm[0][w] = vn0; sm[1][w] = vd0; sm[2][w] = vn1; sm[3][w] = vd1; }
    __syncthreads();

    __shared__ int s_last;
    int bid = (b * 4 + blockIdx.y) * 40 + blockIdx.x;
    if (tid == 0) {
        double aa = 0, bb = 0, cc = 0, dd = 0;
        for (int i = 0; i < 10; i++) { aa += sm[0][i]; bb += sm[1][i]; cc += sm[2][i]; dd += sm[3][i]; }
        g_p2[bid * 4 + 0] = aa;
        g_p2[bid * 4 + 1] = bb;
        g_p2[bid * 4 + 2] = cc;
        g_p2[bid * 4 + 3] = dd;
        __threadfence();
        unsigned t = atomicAdd(&g_cnt, 1);
        s_last = (t == NBLK2 - 1);
    }
    __syncthreads();
    if (s_last) {
        double s0 = 0, s1 = 0, s2 = 0, s3 = 0;
        for (int i = tid; i < NBLK2; i += 320) {
            s0 += g_p2[i * 4 + 0];
            s1 += g_p2[i * 4 + 1];
            s2 += g_p2[i * 4 + 2];
            s3 += g_p2[i * 4 + 3];
        }
        #pragma unroll
        for (int o = 16; o > 0; o >>= 1) {
            s0 += __shfl_down_sync(0xffffffffu, s0, o);
            s1 += __shfl_down_sync(0xffffffffu, s1, o);
            s2 += __shfl_down_sync(0xffffffffu, s2, o);
            s3 += __shfl_down_sync(0xffffffffu, s3, o);
        }
        if (l == 0) { sm[0][w] = s0; sm[1][w] = s1; sm[2][w] = s2; sm[3][w] = s3; }
        __syncthreads();
        if (tid == 0) {
            double aa = 0, bb = 0, cc = 0, dd = 0;
            for (int i = 0; i < 10; i++) { aa += sm[0][i]; bb += sm[1][i]; cc += sm[2][i]; dd += sm[3][i]; }
            double loss = fabs(aa / (bb + 1e-6)) + fabs(cc / (dd + 1e-6));
            out[0] = (float)(2.0 - loss);
            g_cnt = 0;   // reset for next graph replay
        }
    }
}

extern "C" void kernel_launch(void* const* d_in, const int* in_sizes, int n_in,
                              void* d_out, int out_size) {
    const float* lab = (const float*)d_in[0];
    const float* inp = (const float*)d_in[1];
    float* out = (float*)d_out;

    k_A<<<dim3(40, 4, NB), dim3(80, 4)>>>(lab, inp);   // sums + zx-conv(p) + pv pack + means
    k_C<<<dim3(40, 4, NB), dim3(80, 4)>>>(out);        // y-conv + weights + dots + finalize
}